// round 7
// baseline (speedup 1.0000x reference)
#include <cuda_runtime.h>
#include <cuda_bf16.h>
#include <math.h>

// ---------------------------------------------------------------------------
// SwinTransformerBlock: B=32, H=W=56, C=192, NH=6, hd=32, WS=7, SS=3
// N=49 tokens/window, nW=64 windows/img, 2048 windows total, 100352 tokens
// ---------------------------------------------------------------------------

#define Bz   32
#define Hh   56
#define Ww   56
#define Cc   192
#define NHh  6
#define HD   32
#define WSz  7
#define SSz  3
#define Nn   49
#define NWw  64
#define TOK  (Bz * Hh * Ww)      // 100352
#define HID  (4 * Cc)            // 768

// scratch (device globals; allocation-free rule)
__device__ float g_xw[(size_t)TOK * Cc];       // LN1'd, shifted, windowed (reused for LN2 out)
__device__ float g_qkv[(size_t)TOK * 3 * Cc];  // qkv gemm output
__device__ float g_ao[(size_t)TOK * Cc];       // attention output (window layout)
__device__ float g_x2[(size_t)TOK * Cc];       // x + attn_proj (token layout)
__device__ float g_hid[(size_t)TOK * HID];     // fc1+gelu output

// ---------------------------------------------------------------------------
// LN kernel: one block per output token, 192 threads.
// WINDOWED=true : output row = window-token order; src = shifted image coords.
// ---------------------------------------------------------------------------
template <bool WINDOWED>
__global__ void ln_kernel(const float* __restrict__ x,
                          const float* __restrict__ gamma,
                          const float* __restrict__ beta,
                          float* __restrict__ out) {
    int t = blockIdx.x;         // output row
    int c = threadIdx.x;        // channel
    int src = t;
    if (WINDOWED) {
        int w  = t / Nn;        // window id 0..2047
        int n  = t - w * Nn;    // token in window
        int b  = w >> 6;        // /64
        int wi = w & 63;
        int wh = wi >> 3, ww = wi & 7;
        int i = n / WSz, j = n - (n / WSz) * WSz;
        int hs = wh * WSz + i, ws = ww * WSz + j;
        int h = hs + SSz; if (h >= Hh) h -= Hh;
        int wc = ws + SSz; if (wc >= Ww) wc -= Ww;
        src = b * (Hh * Ww) + h * Ww + wc;
    }
    float v = x[(size_t)src * Cc + c];

    float s = v, sq = v * v;
    #pragma unroll
    for (int off = 16; off; off >>= 1) {
        s  += __shfl_down_sync(0xffffffffu, s,  off);
        sq += __shfl_down_sync(0xffffffffu, sq, off);
    }
    __shared__ float ss[6], ssq[6];
    int lane = c & 31, wid = c >> 5;
    if (lane == 0) { ss[wid] = s; ssq[wid] = sq; }
    __syncthreads();
    float tot = 0.f, totq = 0.f;
    #pragma unroll
    for (int i2 = 0; i2 < 6; i2++) { tot += ss[i2]; totq += ssq[i2]; }
    float mean = tot * (1.0f / Cc);
    float var  = totq * (1.0f / Cc) - mean * mean;
    float rstd = rsqrtf(var + 1e-5f);
    out[(size_t)t * Cc + c] = (v - mean) * rstd * gamma[c] + beta[c];
}

// ---------------------------------------------------------------------------
// Tiled SGEMM (double-buffered): C[M,N] = A[M,K] @ B[K,N] (+bias epilogues)
// BM=128, BN=64, BK=16, 256 threads, 8x4 per thread, ping-pong SMEM,
// register-staged global prefetch, one __syncthreads per K-step.
// Requires M%128==0, N%64==0, K%16==0 (true for all calls here).
// EPI: 0=bias  1=bias+window-reverse-scatter+residual  2=bias+exact-gelu
//      3=bias+residual
// ---------------------------------------------------------------------------
template <int EPI>
__global__ __launch_bounds__(256)
void sgemm_kernel(const float* __restrict__ A, const float* __restrict__ Bm,
                  const float* __restrict__ bias, const float* __restrict__ resid,
                  float* __restrict__ C, int M, int N, int K) {
    constexpr int BM = 128, BN = 64, BK = 16;
    __shared__ float As[2][BK][BM];
    __shared__ float Bs[2][BK][BN];
    int tid = threadIdx.x;
    int tx = tid & 15, ty = tid >> 4;
    int m0 = blockIdx.y * BM, n0 = blockIdx.x * BN;

    // per-thread load coordinates
    int aRow0 = tid >> 2;              // A tile rows (2 chunks of 64 rows)
    int aKc   = (tid & 3) << 2;        // k column within tile (float4)
    int bRow  = tid >> 4;              // B tile row
    int bCol  = (tid & 15) << 2;       // B tile col (float4)

    const float* Aptr0 = &A[(size_t)(m0 + aRow0) * K + aKc];
    const float* Aptr1 = &A[(size_t)(m0 + aRow0 + 64) * K + aKc];
    const float* Bptr  = &Bm[(size_t)bRow * N + n0 + bCol];

    float acc[8][4] = {};

    // prologue: load tile 0 into buffer 0
    {
        float4 a0 = *reinterpret_cast<const float4*>(Aptr0);
        float4 a1 = *reinterpret_cast<const float4*>(Aptr1);
        float4 b  = *reinterpret_cast<const float4*>(Bptr);
        As[0][aKc + 0][aRow0] = a0.x; As[0][aKc + 1][aRow0] = a0.y;
        As[0][aKc + 2][aRow0] = a0.z; As[0][aKc + 3][aRow0] = a0.w;
        As[0][aKc + 0][aRow0 + 64] = a1.x; As[0][aKc + 1][aRow0 + 64] = a1.y;
        As[0][aKc + 2][aRow0 + 64] = a1.z; As[0][aKc + 3][aRow0 + 64] = a1.w;
        *reinterpret_cast<float4*>(&Bs[0][bRow][bCol]) = b;
    }
    __syncthreads();

    int buf = 0;
    for (int k0 = 0; k0 < K; k0 += BK) {
        float4 na0, na1, nb;
        bool more = (k0 + BK) < K;
        if (more) {  // prefetch next tile into registers
            na0 = *reinterpret_cast<const float4*>(Aptr0 + k0 + BK);
            na1 = *reinterpret_cast<const float4*>(Aptr1 + k0 + BK);
            nb  = *reinterpret_cast<const float4*>(Bptr + (size_t)(k0 + BK) * N);
        }
        #pragma unroll
        for (int kk = 0; kk < BK; kk++) {
            float a[8], b[4];
            #pragma unroll
            for (int u = 0; u < 8; u++) a[u] = As[buf][kk][ty * 8 + u];
            #pragma unroll
            for (int v = 0; v < 4; v++) b[v] = Bs[buf][kk][tx * 4 + v];
            #pragma unroll
            for (int u = 0; u < 8; u++)
                #pragma unroll
                for (int v = 0; v < 4; v++)
                    acc[u][v] = fmaf(a[u], b[v], acc[u][v]);
        }
        if (more) {
            int nbuf = buf ^ 1;
            As[nbuf][aKc + 0][aRow0] = na0.x; As[nbuf][aKc + 1][aRow0] = na0.y;
            As[nbuf][aKc + 2][aRow0] = na0.z; As[nbuf][aKc + 3][aRow0] = na0.w;
            As[nbuf][aKc + 0][aRow0 + 64] = na1.x; As[nbuf][aKc + 1][aRow0 + 64] = na1.y;
            As[nbuf][aKc + 2][aRow0 + 64] = na1.z; As[nbuf][aKc + 3][aRow0 + 64] = na1.w;
            *reinterpret_cast<float4*>(&Bs[nbuf][bRow][bCol]) = nb;
            __syncthreads();
            buf = nbuf;
        }
    }

    // epilogue: float4 per (u) row; bias + variant op + optional residual
    int ncol = n0 + tx * 4;
    float4 bv = *reinterpret_cast<const float4*>(&bias[ncol]);
    #pragma unroll
    for (int u = 0; u < 8; u++) {
        int m = m0 + ty * 8 + u;
        size_t drow = m;
        if (EPI == 1) {
            // window token -> original image token (window reverse + roll +SS)
            int w  = m / Nn;
            int n  = m - w * Nn;
            int b  = w >> 6;
            int wi = w & 63;
            int wh = wi >> 3, ww = wi & 7;
            int i = n / WSz, j = n - (n / WSz) * WSz;
            int hs = wh * WSz + i, ws = ww * WSz + j;
            int h = hs + SSz; if (h >= Hh) h -= Hh;
            int wc = ws + SSz; if (wc >= Ww) wc -= Ww;
            drow = (size_t)(b * (Hh * Ww) + h * Ww + wc);
        }
        float4 val;
        val.x = acc[u][0] + bv.x;
        val.y = acc[u][1] + bv.y;
        val.z = acc[u][2] + bv.z;
        val.w = acc[u][3] + bv.w;
        if (EPI == 2) {
            const float r = 0.70710678118654752f;
            val.x = 0.5f * val.x * (1.0f + erff(val.x * r));
            val.y = 0.5f * val.y * (1.0f + erff(val.y * r));
            val.z = 0.5f * val.z * (1.0f + erff(val.z * r));
            val.w = 0.5f * val.w * (1.0f + erff(val.w * r));
        }
        if (EPI == 1 || EPI == 3) {
            float4 rv = *reinterpret_cast<const float4*>(&resid[drow * N + ncol]);
            val.x += rv.x; val.y += rv.y; val.z += rv.z; val.w += rv.w;
        }
        *reinterpret_cast<float4*>(&C[drow * N + ncol]) = val;
    }
}

// ---------------------------------------------------------------------------
// Windowed attention: one block per (window, head). 128 threads.
// q,k,v in SMEM (49x32 each) + 49x49 score matrix. Bias + shift-mask inline.
// float4-vectorized SMEM/global traffic (all offsets 16B-aligned).
// ---------------------------------------------------------------------------
__global__ __launch_bounds__(128)
void attn_kernel(const float* __restrict__ qkv,
                 const float* __restrict__ rel_bias,
                 float* __restrict__ out) {
    __shared__ float qs[Nn * HD], ks[Nn * HD], vs[Nn * HD], sc[Nn * Nn];
    int w = blockIdx.x / NHh;
    int h = blockIdx.x - w * NHh;
    int tid = threadIdx.x;
    const float scale = 0.17677669529663687f;  // 1/sqrt(32)
    const float* base = qkv + (size_t)w * Nn * (3 * Cc) + h * HD;

    // staged gather: 49*32/4 = 392 float4 per tensor
    for (int i = tid; i < Nn * HD / 4; i += 128) {
        int n = i >> 3, d4 = (i & 7) << 2;           // row, float4 col
        const float* row = base + (size_t)n * (3 * Cc) + d4;
        float4 q4 = *reinterpret_cast<const float4*>(row);
        float4 k4 = *reinterpret_cast<const float4*>(row + Cc);
        float4 v4 = *reinterpret_cast<const float4*>(row + 2 * Cc);
        q4.x *= scale; q4.y *= scale; q4.z *= scale; q4.w *= scale;
        *reinterpret_cast<float4*>(&qs[n * HD + d4]) = q4;
        *reinterpret_cast<float4*>(&ks[n * HD + d4]) = k4;
        *reinterpret_cast<float4*>(&vs[n * HD + d4]) = v4;
    }
    int wi = w & 63;
    int wh = wi >> 3, ww = wi & 7;
    __syncthreads();

    for (int idx = tid; idx < Nn * Nn; idx += 128) {
        int n = idx / Nn, m = idx - (idx / Nn) * Nn;
        float s = 0.f;
        #pragma unroll
        for (int d = 0; d < HD; d += 4) {
            float4 q4 = *reinterpret_cast<const float4*>(&qs[n * HD + d]);
            float4 k4 = *reinterpret_cast<const float4*>(&ks[m * HD + d]);
            s = fmaf(q4.x, k4.x, s); s = fmaf(q4.y, k4.y, s);
            s = fmaf(q4.z, k4.z, s); s = fmaf(q4.w, k4.w, s);
        }
        int ni = n / WSz, nj = n - ni * WSz;
        int mi = m / WSz, mj = m - mi * WSz;
        s += rel_bias[((ni - mi + WSz - 1) * (2 * WSz - 1) + (nj - mj + WSz - 1)) * NHh + h];
        // shift mask: region id of shifted coords
        int hn = wh * WSz + ni, hm = wh * WSz + mi;
        int wn = ww * WSz + nj, wm = ww * WSz + mj;
        int rn = (hn < Hh - WSz) ? 0 : ((hn < Hh - SSz) ? 1 : 2);
        int rm = (hm < Hh - WSz) ? 0 : ((hm < Hh - SSz) ? 1 : 2);
        int cn = (wn < Ww - WSz) ? 0 : ((wn < Ww - SSz) ? 1 : 2);
        int cm = (wm < Ww - WSz) ? 0 : ((wm < Ww - SSz) ? 1 : 2);
        if (rn != rm || cn != cm) s -= 100.0f;
        sc[idx] = s;
    }
    __syncthreads();

    int warp = tid >> 5, lane = tid & 31;
    for (int r = warp; r < Nn; r += 4) {
        float v1 = sc[r * Nn + lane];
        float v2 = (lane + 32 < Nn) ? sc[r * Nn + lane + 32] : -1e30f;
        float mx = fmaxf(v1, v2);
        #pragma unroll
        for (int off = 16; off; off >>= 1)
            mx = fmaxf(mx, __shfl_xor_sync(0xffffffffu, mx, off));
        float e1 = expf(v1 - mx);
        float e2 = (lane + 32 < Nn) ? expf(v2 - mx) : 0.f;
        float s = e1 + e2;
        #pragma unroll
        for (int off = 16; off; off >>= 1)
            s += __shfl_xor_sync(0xffffffffu, s, off);
        float inv = 1.0f / s;
        sc[r * Nn + lane] = e1 * inv;
        if (lane + 32 < Nn) sc[r * Nn + lane + 32] = e2 * inv;
    }
    __syncthreads();

    // out = P @ V : each thread does one (n,d) with d-vectorized V reads
    for (int i = tid; i < Nn * HD; i += 128) {
        int n = i >> 5, d = i & 31;
        float s = 0.f;
        #pragma unroll
        for (int m = 0; m < Nn; m++) s = fmaf(sc[n * Nn + m], vs[m * HD + d], s);
        out[((size_t)w * Nn + n) * Cc + h * HD + d] = s;
    }
}

// ---------------------------------------------------------------------------
extern "C" void kernel_launch(void* const* d_in, const int* in_sizes, int n_in,
                              void* d_out, int out_size) {
    const float* x       = (const float*)d_in[0];
    const float* n1g     = (const float*)d_in[1];
    const float* n1b     = (const float*)d_in[2];
    const float* qkv_w   = (const float*)d_in[3];
    const float* qkv_b   = (const float*)d_in[4];
    const float* relb    = (const float*)d_in[5];
    const float* proj_w  = (const float*)d_in[6];
    const float* proj_b  = (const float*)d_in[7];
    const float* n2g     = (const float*)d_in[8];
    const float* n2b     = (const float*)d_in[9];
    const float* fc1_w   = (const float*)d_in[10];
    const float* fc1_b   = (const float*)d_in[11];
    const float* fc2_w   = (const float*)d_in[12];
    const float* fc2_b   = (const float*)d_in[13];
    float* out = (float*)d_out;

    float *xw, *qkv, *ao, *x2, *hid;
    cudaGetSymbolAddress((void**)&xw,  g_xw);
    cudaGetSymbolAddress((void**)&qkv, g_qkv);
    cudaGetSymbolAddress((void**)&ao,  g_ao);
    cudaGetSymbolAddress((void**)&x2,  g_x2);
    cudaGetSymbolAddress((void**)&hid, g_hid);

    const int M = TOK;  // 100352

    // 1) LN1 + shift + window partition
    ln_kernel<true><<<M, Cc>>>(x, n1g, n1b, xw);

    // 2) QKV gemm: [M,192] @ [192,576]
    sgemm_kernel<0><<<dim3(3 * Cc / 64, M / 128), 256>>>(
        xw, qkv_w, qkv_b, nullptr, qkv, M, 3 * Cc, Cc);

    // 3) windowed attention (2048 windows x 6 heads)
    attn_kernel<<<2048 * NHh, 128>>>(qkv, relb, ao);

    // 4) proj gemm + window reverse + un-shift + residual -> x2
    sgemm_kernel<1><<<dim3(Cc / 64, M / 128), 256>>>(
        ao, proj_w, proj_b, x, x2, M, Cc, Cc);

    // 5) LN2 (reuse xw buffer)
    ln_kernel<false><<<M, Cc>>>(x2, n2g, n2b, xw);

    // 6) fc1 + exact gelu: [M,192] @ [192,768]
    sgemm_kernel<2><<<dim3(HID / 64, M / 128), 256>>>(
        xw, fc1_w, fc1_b, nullptr, hid, M, HID, Cc);

    // 7) fc2 + residual: [M,768] @ [768,192] -> out
    sgemm_kernel<3><<<dim3(Cc / 64, M / 128), 256>>>(
        hid, fc2_w, fc2_b, x2, out, M, Cc, HID);
}

// round 8
// speedup vs baseline: 1.3424x; 1.3424x over previous
#include <cuda_runtime.h>
#include <cuda_bf16.h>
#include <math.h>
#include <stdint.h>

// ---------------------------------------------------------------------------
// SwinTransformerBlock: B=32, H=W=56, C=192, NH=6, hd=32, WS=7, SS=3
// GEMMs on tensor cores via mma.sync.m16n8k8 tf32 (fp32 accumulate).
// ---------------------------------------------------------------------------

#define Bz   32
#define Hh   56
#define Ww   56
#define Cc   192
#define NHh  6
#define HD   32
#define WSz  7
#define SSz  3
#define Nn   49
#define NWw  64
#define TOK  (Bz * Hh * Ww)      // 100352
#define HID  (4 * Cc)            // 768

__device__ float g_xw[(size_t)TOK * Cc];
__device__ float g_qkv[(size_t)TOK * 3 * Cc];
__device__ float g_ao[(size_t)TOK * Cc];
__device__ float g_x2[(size_t)TOK * Cc];
__device__ float g_hid[(size_t)TOK * HID];

// ---------------------------------------------------------------------------
template <bool WINDOWED>
__global__ void ln_kernel(const float* __restrict__ x,
                          const float* __restrict__ gamma,
                          const float* __restrict__ beta,
                          float* __restrict__ out) {
    int t = blockIdx.x;
    int c = threadIdx.x;
    int src = t;
    if (WINDOWED) {
        int w  = t / Nn;
        int n  = t - w * Nn;
        int b  = w >> 6;
        int wi = w & 63;
        int wh = wi >> 3, ww = wi & 7;
        int i = n / WSz, j = n - (n / WSz) * WSz;
        int hs = wh * WSz + i, ws = ww * WSz + j;
        int h = hs + SSz; if (h >= Hh) h -= Hh;
        int wc = ws + SSz; if (wc >= Ww) wc -= Ww;
        src = b * (Hh * Ww) + h * Ww + wc;
    }
    float v = x[(size_t)src * Cc + c];

    float s = v, sq = v * v;
    #pragma unroll
    for (int off = 16; off; off >>= 1) {
        s  += __shfl_down_sync(0xffffffffu, s,  off);
        sq += __shfl_down_sync(0xffffffffu, sq, off);
    }
    __shared__ float ss[6], ssq[6];
    int lane = c & 31, wid = c >> 5;
    if (lane == 0) { ss[wid] = s; ssq[wid] = sq; }
    __syncthreads();
    float tot = 0.f, totq = 0.f;
    #pragma unroll
    for (int i2 = 0; i2 < 6; i2++) { tot += ss[i2]; totq += ssq[i2]; }
    float mean = tot * (1.0f / Cc);
    float var  = totq * (1.0f / Cc) - mean * mean;
    float rstd = rsqrtf(var + 1e-5f);
    out[(size_t)t * Cc + c] = (v - mean) * rstd * gamma[c] + beta[c];
}

// ---------------------------------------------------------------------------
// tf32 helpers
// ---------------------------------------------------------------------------
__device__ __forceinline__ float ftf32(float x) {
    uint32_t u;
    asm("cvt.rna.tf32.f32 %0, %1;" : "=r"(u) : "f"(x));
    return __uint_as_float(u);
}

__device__ __forceinline__ void mma_tf32(float* c, const uint32_t* a, const uint32_t* b) {
    asm volatile(
        "mma.sync.aligned.m16n8k8.row.col.f32.tf32.tf32.f32 "
        "{%0,%1,%2,%3}, {%4,%5,%6,%7}, {%8,%9}, {%0,%1,%2,%3};\n"
        : "+f"(c[0]), "+f"(c[1]), "+f"(c[2]), "+f"(c[3])
        : "r"(a[0]), "r"(a[1]), "r"(a[2]), "r"(a[3]),
          "r"(b[0]), "r"(b[1]));
}

// ---------------------------------------------------------------------------
// TF32 tensor-core GEMM: C[M,N] = A[M,K] @ B[K,N] (+bias epilogues)
// BM=128, BN=64, BK=16, 256 threads = 8 warps (4x2), warp tile 32x32.
// Double-buffered SMEM, register-staged global prefetch.
// As: [BK][132] (k-major, A stored transposed, tf32-rounded)
// Bs: [BK][68]  (natural, float4 stores, tf32-rounded)
// EPI: 0=bias 1=bias+window-reverse-scatter+residual 2=bias+gelu 3=bias+residual
// ---------------------------------------------------------------------------
template <int EPI>
__global__ __launch_bounds__(256)
void tgemm_kernel(const float* __restrict__ A, const float* __restrict__ Bm,
                  const float* __restrict__ bias, const float* __restrict__ resid,
                  float* __restrict__ C, int M, int N, int K) {
    constexpr int BM = 128, BN = 64, BK = 16;
    constexpr int ASTR = 132, BSTR = 68;
    __shared__ float As[2][BK][ASTR];
    __shared__ float Bs[2][BK][BSTR];

    int tid = threadIdx.x;
    int lane = tid & 31;
    int wid  = tid >> 5;
    int warp_m = wid & 3;          // 0..3 -> 32-row band
    int warp_n = wid >> 2;         // 0..1 -> 32-col band
    int m0 = blockIdx.y * BM, n0 = blockIdx.x * BN;

    // global load coords (identical pattern to fp32 version)
    int aRow0 = tid >> 2;          // 0..63 (two bands of 64 rows)
    int aKc   = (tid & 3) << 2;    // k column (float4)
    int bRow  = tid >> 4;          // 0..15
    int bCol  = (tid & 15) << 2;   // col (float4)

    const float* Aptr0 = &A[(size_t)(m0 + aRow0) * K + aKc];
    const float* Aptr1 = &A[(size_t)(m0 + aRow0 + 64) * K + aKc];
    const float* Bptr  = &Bm[(size_t)bRow * N + n0 + bCol];

    float acc[2][4][4];            // [mf][nf][reg]
    #pragma unroll
    for (int i = 0; i < 2; i++)
        #pragma unroll
        for (int j = 0; j < 4; j++)
            #pragma unroll
            for (int r = 0; r < 4; r++) acc[i][j][r] = 0.f;

    // prologue: tile 0 -> buffer 0 (tf32-rounded at store)
    {
        float4 a0 = *reinterpret_cast<const float4*>(Aptr0);
        float4 a1 = *reinterpret_cast<const float4*>(Aptr1);
        float4 b  = *reinterpret_cast<const float4*>(Bptr);
        As[0][aKc + 0][aRow0] = ftf32(a0.x); As[0][aKc + 1][aRow0] = ftf32(a0.y);
        As[0][aKc + 2][aRow0] = ftf32(a0.z); As[0][aKc + 3][aRow0] = ftf32(a0.w);
        As[0][aKc + 0][aRow0 + 64] = ftf32(a1.x); As[0][aKc + 1][aRow0 + 64] = ftf32(a1.y);
        As[0][aKc + 2][aRow0 + 64] = ftf32(a1.z); As[0][aKc + 3][aRow0 + 64] = ftf32(a1.w);
        float4 bc; bc.x = ftf32(b.x); bc.y = ftf32(b.y); bc.z = ftf32(b.z); bc.w = ftf32(b.w);
        *reinterpret_cast<float4*>(&Bs[0][bRow][bCol]) = bc;
    }
    __syncthreads();

    int mbase = warp_m * 32;
    int nbase = warp_n * 32;
    int lrow = lane >> 2;          // 0..7
    int lcol = lane & 3;           // 0..3

    int buf = 0;
    for (int k0 = 0; k0 < K; k0 += BK) {
        float4 na0, na1, nb;
        bool more = (k0 + BK) < K;
        if (more) {
            na0 = *reinterpret_cast<const float4*>(Aptr0 + k0 + BK);
            na1 = *reinterpret_cast<const float4*>(Aptr1 + k0 + BK);
            nb  = *reinterpret_cast<const float4*>(Bptr + (size_t)(k0 + BK) * N);
        }

        #pragma unroll
        for (int ks = 0; ks < BK; ks += 8) {
            // A fragments: mf in {0,1} covers rows mbase+mf*16 .. +15
            uint32_t afr[2][4];
            #pragma unroll
            for (int mf = 0; mf < 2; mf++) {
                int rb = mbase + mf * 16 + lrow;
                afr[mf][0] = __float_as_uint(As[buf][ks + lcol    ][rb]);
                afr[mf][1] = __float_as_uint(As[buf][ks + lcol    ][rb + 8]);
                afr[mf][2] = __float_as_uint(As[buf][ks + 4 + lcol][rb]);
                afr[mf][3] = __float_as_uint(As[buf][ks + 4 + lcol][rb + 8]);
            }
            // B fragments: nf in {0..3} covers cols nbase+nf*8 .. +7
            uint32_t bfr[4][2];
            #pragma unroll
            for (int nf = 0; nf < 4; nf++) {
                int cb = nbase + nf * 8 + lrow;
                bfr[nf][0] = __float_as_uint(Bs[buf][ks + lcol    ][cb]);
                bfr[nf][1] = __float_as_uint(Bs[buf][ks + 4 + lcol][cb]);
            }
            #pragma unroll
            for (int mf = 0; mf < 2; mf++)
                #pragma unroll
                for (int nf = 0; nf < 4; nf++)
                    mma_tf32(acc[mf][nf], afr[mf], bfr[nf]);
        }

        if (more) {
            int nbuf = buf ^ 1;
            As[nbuf][aKc + 0][aRow0] = ftf32(na0.x); As[nbuf][aKc + 1][aRow0] = ftf32(na0.y);
            As[nbuf][aKc + 2][aRow0] = ftf32(na0.z); As[nbuf][aKc + 3][aRow0] = ftf32(na0.w);
            As[nbuf][aKc + 0][aRow0 + 64] = ftf32(na1.x); As[nbuf][aKc + 1][aRow0 + 64] = ftf32(na1.y);
            As[nbuf][aKc + 2][aRow0 + 64] = ftf32(na1.z); As[nbuf][aKc + 3][aRow0 + 64] = ftf32(na1.w);
            float4 bc; bc.x = ftf32(nb.x); bc.y = ftf32(nb.y); bc.z = ftf32(nb.z); bc.w = ftf32(nb.w);
            *reinterpret_cast<float4*>(&Bs[nbuf][bRow][bCol]) = bc;
            __syncthreads();
            buf = nbuf;
        }
    }

    // ------------------------------------------------------------------
    // epilogue: per C fragment element.
    // c0,c1 -> row lrow;  c2,c3 -> row lrow+8;  cols 2*lcol, 2*lcol+1
    // ------------------------------------------------------------------
    #pragma unroll
    for (int mf = 0; mf < 2; mf++) {
        #pragma unroll
        for (int half = 0; half < 2; half++) {   // half=0: c0/c1, half=1: c2/c3
            int m = m0 + mbase + mf * 16 + lrow + half * 8;
            size_t drow = m;
            if (EPI == 1) {
                int w  = m / Nn;
                int n  = m - w * Nn;
                int b  = w >> 6;
                int wi = w & 63;
                int wh = wi >> 3, ww = wi & 7;
                int i = n / WSz, j = n - (n / WSz) * WSz;
                int hs = wh * WSz + i, ws = ww * WSz + j;
                int h = hs + SSz; if (h >= Hh) h -= Hh;
                int wc = ws + SSz; if (wc >= Ww) wc -= Ww;
                drow = (size_t)(b * (Hh * Ww) + h * Ww + wc);
            }
            #pragma unroll
            for (int nf = 0; nf < 4; nf++) {
                int col = n0 + nbase + nf * 8 + 2 * lcol;
                float2 val;
                val.x = acc[mf][nf][2 * half + 0] + bias[col];
                val.y = acc[mf][nf][2 * half + 1] + bias[col + 1];
                if (EPI == 2) {
                    const float r = 0.70710678118654752f;
                    val.x = 0.5f * val.x * (1.0f + erff(val.x * r));
                    val.y = 0.5f * val.y * (1.0f + erff(val.y * r));
                }
                if (EPI == 1 || EPI == 3) {
                    float2 rv = *reinterpret_cast<const float2*>(&resid[drow * N + col]);
                    val.x += rv.x; val.y += rv.y;
                }
                *reinterpret_cast<float2*>(&C[drow * N + col]) = val;
            }
        }
    }
}

// ---------------------------------------------------------------------------
// Windowed attention (unchanged, fp32)
// ---------------------------------------------------------------------------
__global__ __launch_bounds__(128)
void attn_kernel(const float* __restrict__ qkv,
                 const float* __restrict__ rel_bias,
                 float* __restrict__ out) {
    __shared__ float qs[Nn * HD], ks[Nn * HD], vs[Nn * HD], sc[Nn * Nn];
    int w = blockIdx.x / NHh;
    int h = blockIdx.x - w * NHh;
    int tid = threadIdx.x;
    const float scale = 0.17677669529663687f;
    const float* base = qkv + (size_t)w * Nn * (3 * Cc) + h * HD;

    for (int i = tid; i < Nn * HD / 4; i += 128) {
        int n = i >> 3, d4 = (i & 7) << 2;
        const float* row = base + (size_t)n * (3 * Cc) + d4;
        float4 q4 = *reinterpret_cast<const float4*>(row);
        float4 k4 = *reinterpret_cast<const float4*>(row + Cc);
        float4 v4 = *reinterpret_cast<const float4*>(row + 2 * Cc);
        q4.x *= scale; q4.y *= scale; q4.z *= scale; q4.w *= scale;
        *reinterpret_cast<float4*>(&qs[n * HD + d4]) = q4;
        *reinterpret_cast<float4*>(&ks[n * HD + d4]) = k4;
        *reinterpret_cast<float4*>(&vs[n * HD + d4]) = v4;
    }
    int wi = w & 63;
    int wh = wi >> 3, ww = wi & 7;
    __syncthreads();

    for (int idx = tid; idx < Nn * Nn; idx += 128) {
        int n = idx / Nn, m = idx - (idx / Nn) * Nn;
        float s = 0.f;
        #pragma unroll
        for (int d = 0; d < HD; d += 4) {
            float4 q4 = *reinterpret_cast<const float4*>(&qs[n * HD + d]);
            float4 k4 = *reinterpret_cast<const float4*>(&ks[m * HD + d]);
            s = fmaf(q4.x, k4.x, s); s = fmaf(q4.y, k4.y, s);
            s = fmaf(q4.z, k4.z, s); s = fmaf(q4.w, k4.w, s);
        }
        int ni = n / WSz, nj = n - ni * WSz;
        int mi = m / WSz, mj = m - mi * WSz;
        s += rel_bias[((ni - mi + WSz - 1) * (2 * WSz - 1) + (nj - mj + WSz - 1)) * NHh + h];
        int hn = wh * WSz + ni, hm = wh * WSz + mi;
        int wn = ww * WSz + nj, wm = ww * WSz + mj;
        int rn = (hn < Hh - WSz) ? 0 : ((hn < Hh - SSz) ? 1 : 2);
        int rm = (hm < Hh - WSz) ? 0 : ((hm < Hh - SSz) ? 1 : 2);
        int cn = (wn < Ww - WSz) ? 0 : ((wn < Ww - SSz) ? 1 : 2);
        int cm = (wm < Ww - WSz) ? 0 : ((wm < Ww - SSz) ? 1 : 2);
        if (rn != rm || cn != cm) s -= 100.0f;
        sc[idx] = s;
    }
    __syncthreads();

    int warp = tid >> 5, lane = tid & 31;
    for (int r = warp; r < Nn; r += 4) {
        float v1 = sc[r * Nn + lane];
        float v2 = (lane + 32 < Nn) ? sc[r * Nn + lane + 32] : -1e30f;
        float mx = fmaxf(v1, v2);
        #pragma unroll
        for (int off = 16; off; off >>= 1)
            mx = fmaxf(mx, __shfl_xor_sync(0xffffffffu, mx, off));
        float e1 = expf(v1 - mx);
        float e2 = (lane + 32 < Nn) ? expf(v2 - mx) : 0.f;
        float s = e1 + e2;
        #pragma unroll
        for (int off = 16; off; off >>= 1)
            s += __shfl_xor_sync(0xffffffffu, s, off);
        float inv = 1.0f / s;
        sc[r * Nn + lane] = e1 * inv;
        if (lane + 32 < Nn) sc[r * Nn + lane + 32] = e2 * inv;
    }
    __syncthreads();

    for (int i = tid; i < Nn * HD; i += 128) {
        int n = i >> 5, d = i & 31;
        float s = 0.f;
        #pragma unroll
        for (int m = 0; m < Nn; m++) s = fmaf(sc[n * Nn + m], vs[m * HD + d], s);
        out[((size_t)w * Nn + n) * Cc + h * HD + d] = s;
    }
}

// ---------------------------------------------------------------------------
extern "C" void kernel_launch(void* const* d_in, const int* in_sizes, int n_in,
                              void* d_out, int out_size) {
    const float* x       = (const float*)d_in[0];
    const float* n1g     = (const float*)d_in[1];
    const float* n1b     = (const float*)d_in[2];
    const float* qkv_w   = (const float*)d_in[3];
    const float* qkv_b   = (const float*)d_in[4];
    const float* relb    = (const float*)d_in[5];
    const float* proj_w  = (const float*)d_in[6];
    const float* proj_b  = (const float*)d_in[7];
    const float* n2g     = (const float*)d_in[8];
    const float* n2b     = (const float*)d_in[9];
    const float* fc1_w   = (const float*)d_in[10];
    const float* fc1_b   = (const float*)d_in[11];
    const float* fc2_w   = (const float*)d_in[12];
    const float* fc2_b   = (const float*)d_in[13];
    float* out = (float*)d_out;

    float *xw, *qkv, *ao, *x2, *hid;
    cudaGetSymbolAddress((void**)&xw,  g_xw);
    cudaGetSymbolAddress((void**)&qkv, g_qkv);
    cudaGetSymbolAddress((void**)&ao,  g_ao);
    cudaGetSymbolAddress((void**)&x2,  g_x2);
    cudaGetSymbolAddress((void**)&hid, g_hid);

    const int M = TOK;  // 100352

    ln_kernel<true><<<M, Cc>>>(x, n1g, n1b, xw);

    tgemm_kernel<0><<<dim3(3 * Cc / 64, M / 128), 256>>>(
        xw, qkv_w, qkv_b, nullptr, qkv, M, 3 * Cc, Cc);

    attn_kernel<<<2048 * NHh, 128>>>(qkv, relb, ao);

    tgemm_kernel<1><<<dim3(Cc / 64, M / 128), 256>>>(
        ao, proj_w, proj_b, x, x2, M, Cc, Cc);

    ln_kernel<false><<<M, Cc>>>(x2, n2g, n2b, xw);

    tgemm_kernel<2><<<dim3(HID / 64, M / 128), 256>>>(
        xw, fc1_w, fc1_b, nullptr, hid, M, HID, Cc);

    tgemm_kernel<3><<<dim3(Cc / 64, M / 128), 256>>>(
        hid, fc2_w, fc2_b, x2, out, M, Cc, HID);
}

// round 9
// speedup vs baseline: 1.4515x; 1.0813x over previous
#include <cuda_runtime.h>
#include <cuda_bf16.h>
#include <math.h>
#include <stdint.h>

// ---------------------------------------------------------------------------
// SwinTransformerBlock: B=32, H=W=56, C=192, NH=6, hd=32, WS=7, SS=3
// GEMMs on tensor cores via mma.sync.m16n8k8 tf32 (fp32 accumulate).
// R9: conflict-free SMEM strides (≡8 mod 32) + BM=256 / warp tile 64x32.
// ---------------------------------------------------------------------------

#define Bz   32
#define Hh   56
#define Ww   56
#define Cc   192
#define NHh  6
#define HD   32
#define WSz  7
#define SSz  3
#define Nn   49
#define NWw  64
#define TOK  (Bz * Hh * Ww)      // 100352
#define HID  (4 * Cc)            // 768

__device__ float g_xw[(size_t)TOK * Cc];
__device__ float g_qkv[(size_t)TOK * 3 * Cc];
__device__ float g_ao[(size_t)TOK * Cc];
__device__ float g_x2[(size_t)TOK * Cc];
__device__ float g_hid[(size_t)TOK * HID];

// ---------------------------------------------------------------------------
template <bool WINDOWED>
__global__ void ln_kernel(const float* __restrict__ x,
                          const float* __restrict__ gamma,
                          const float* __restrict__ beta,
                          float* __restrict__ out) {
    int t = blockIdx.x;
    int c = threadIdx.x;
    int src = t;
    if (WINDOWED) {
        int w  = t / Nn;
        int n  = t - w * Nn;
        int b  = w >> 6;
        int wi = w & 63;
        int wh = wi >> 3, ww = wi & 7;
        int i = n / WSz, j = n - (n / WSz) * WSz;
        int hs = wh * WSz + i, ws = ww * WSz + j;
        int h = hs + SSz; if (h >= Hh) h -= Hh;
        int wc = ws + SSz; if (wc >= Ww) wc -= Ww;
        src = b * (Hh * Ww) + h * Ww + wc;
    }
    float v = x[(size_t)src * Cc + c];

    float s = v, sq = v * v;
    #pragma unroll
    for (int off = 16; off; off >>= 1) {
        s  += __shfl_down_sync(0xffffffffu, s,  off);
        sq += __shfl_down_sync(0xffffffffu, sq, off);
    }
    __shared__ float ss[6], ssq[6];
    int lane = c & 31, wid = c >> 5;
    if (lane == 0) { ss[wid] = s; ssq[wid] = sq; }
    __syncthreads();
    float tot = 0.f, totq = 0.f;
    #pragma unroll
    for (int i2 = 0; i2 < 6; i2++) { tot += ss[i2]; totq += ssq[i2]; }
    float mean = tot * (1.0f / Cc);
    float var  = totq * (1.0f / Cc) - mean * mean;
    float rstd = rsqrtf(var + 1e-5f);
    out[(size_t)t * Cc + c] = (v - mean) * rstd * gamma[c] + beta[c];
}

// ---------------------------------------------------------------------------
__device__ __forceinline__ float ftf32(float x) {
    uint32_t u;
    asm("cvt.rna.tf32.f32 %0, %1;" : "=r"(u) : "f"(x));
    return __uint_as_float(u);
}

__device__ __forceinline__ void mma_tf32(float* c, const uint32_t* a, const uint32_t* b) {
    asm volatile(
        "mma.sync.aligned.m16n8k8.row.col.f32.tf32.tf32.f32 "
        "{%0,%1,%2,%3}, {%4,%5,%6,%7}, {%8,%9}, {%0,%1,%2,%3};\n"
        : "+f"(c[0]), "+f"(c[1]), "+f"(c[2]), "+f"(c[3])
        : "r"(a[0]), "r"(a[1]), "r"(a[2]), "r"(a[3]),
          "r"(b[0]), "r"(b[1]));
}

// ---------------------------------------------------------------------------
// TF32 tensor-core GEMM: C[M,N] = A[M,K] @ B[K,N] (+bias epilogues)
// BM=256, BN=64, BK=16, 256 threads = 8 warps (4x2), warp tile 64x32
// (mf=4 x nf=4 m16n8k8 fragments). Double-buffered, conflict-free strides
// (ASTR=264, BSTR=72; both ≡8 mod 32 so lcol*8+lrow covers banks 0..31).
// Requires M%256==0, N%64==0, K%16==0.
// EPI: 0=bias 1=bias+window-reverse-scatter+residual 2=bias+gelu 3=bias+residual
// ---------------------------------------------------------------------------
template <int EPI>
__global__ __launch_bounds__(256)
void tgemm_kernel(const float* __restrict__ A, const float* __restrict__ Bm,
                  const float* __restrict__ bias, const float* __restrict__ resid,
                  float* __restrict__ C, int M, int N, int K) {
    constexpr int BM = 256, BN = 64, BK = 16;
    constexpr int ASTR = 264, BSTR = 72;
    __shared__ float As[2][BK][ASTR];
    __shared__ float Bs[2][BK][BSTR];

    int tid = threadIdx.x;
    int lane = tid & 31;
    int wid  = tid >> 5;
    int warp_m = wid & 3;          // 0..3 -> 64-row band
    int warp_n = wid >> 2;         // 0..1 -> 32-col band
    int m0 = blockIdx.y * BM, n0 = blockIdx.x * BN;

    // global load coords
    int aRow0 = tid >> 2;          // 0..63 (4 bands of 64 rows)
    int aKc   = (tid & 3) << 2;    // k column (float4)
    int bRow  = tid >> 4;          // 0..15
    int bCol  = (tid & 15) << 2;   // col (float4)

    const float* Ap[4];
    #pragma unroll
    for (int c = 0; c < 4; c++)
        Ap[c] = &A[(size_t)(m0 + aRow0 + c * 64) * K + aKc];
    const float* Bptr = &Bm[(size_t)bRow * N + n0 + bCol];

    float acc[4][4][4];            // [mf][nf][reg]
    #pragma unroll
    for (int i = 0; i < 4; i++)
        #pragma unroll
        for (int j = 0; j < 4; j++)
            #pragma unroll
            for (int r = 0; r < 4; r++) acc[i][j][r] = 0.f;

    // prologue: tile 0 -> buffer 0 (tf32-rounded at store)
    {
        #pragma unroll
        for (int c = 0; c < 4; c++) {
            float4 a = *reinterpret_cast<const float4*>(Ap[c]);
            int row = aRow0 + c * 64;
            As[0][aKc + 0][row] = ftf32(a.x); As[0][aKc + 1][row] = ftf32(a.y);
            As[0][aKc + 2][row] = ftf32(a.z); As[0][aKc + 3][row] = ftf32(a.w);
        }
        float4 b = *reinterpret_cast<const float4*>(Bptr);
        float4 bc; bc.x = ftf32(b.x); bc.y = ftf32(b.y); bc.z = ftf32(b.z); bc.w = ftf32(b.w);
        *reinterpret_cast<float4*>(&Bs[0][bRow][bCol]) = bc;
    }
    __syncthreads();

    int mbase = warp_m * 64;
    int nbase = warp_n * 32;
    int lrow = lane >> 2;          // 0..7
    int lcol = lane & 3;           // 0..3

    int buf = 0;
    for (int k0 = 0; k0 < K; k0 += BK) {
        float4 na[4], nb;
        bool more = (k0 + BK) < K;
        if (more) {
            #pragma unroll
            for (int c = 0; c < 4; c++)
                na[c] = *reinterpret_cast<const float4*>(Ap[c] + k0 + BK);
            nb = *reinterpret_cast<const float4*>(Bptr + (size_t)(k0 + BK) * N);
        }

        #pragma unroll
        for (int ks = 0; ks < BK; ks += 8) {
            uint32_t afr[4][4];
            #pragma unroll
            for (int mf = 0; mf < 4; mf++) {
                int rb = mbase + mf * 16 + lrow;
                afr[mf][0] = __float_as_uint(As[buf][ks + lcol    ][rb]);
                afr[mf][1] = __float_as_uint(As[buf][ks + lcol    ][rb + 8]);
                afr[mf][2] = __float_as_uint(As[buf][ks + 4 + lcol][rb]);
                afr[mf][3] = __float_as_uint(As[buf][ks + 4 + lcol][rb + 8]);
            }
            uint32_t bfr[4][2];
            #pragma unroll
            for (int nf = 0; nf < 4; nf++) {
                int cb = nbase + nf * 8 + lrow;
                bfr[nf][0] = __float_as_uint(Bs[buf][ks + lcol    ][cb]);
                bfr[nf][1] = __float_as_uint(Bs[buf][ks + 4 + lcol][cb]);
            }
            #pragma unroll
            for (int mf = 0; mf < 4; mf++)
                #pragma unroll
                for (int nf = 0; nf < 4; nf++)
                    mma_tf32(acc[mf][nf], afr[mf], bfr[nf]);
        }

        if (more) {
            int nbuf = buf ^ 1;
            #pragma unroll
            for (int c = 0; c < 4; c++) {
                int row = aRow0 + c * 64;
                As[nbuf][aKc + 0][row] = ftf32(na[c].x); As[nbuf][aKc + 1][row] = ftf32(na[c].y);
                As[nbuf][aKc + 2][row] = ftf32(na[c].z); As[nbuf][aKc + 3][row] = ftf32(na[c].w);
            }
            float4 bc; bc.x = ftf32(nb.x); bc.y = ftf32(nb.y); bc.z = ftf32(nb.z); bc.w = ftf32(nb.w);
            *reinterpret_cast<float4*>(&Bs[nbuf][bRow][bCol]) = bc;
            __syncthreads();
            buf = nbuf;
        }
    }

    // ------------------------------------------------------------------
    // epilogue: c0,c1 -> row lrow; c2,c3 -> row lrow+8; cols 2*lcol(+1)
    // ------------------------------------------------------------------
    #pragma unroll
    for (int mf = 0; mf < 4; mf++) {
        #pragma unroll
        for (int half = 0; half < 2; half++) {
            int m = m0 + mbase + mf * 16 + lrow + half * 8;
            size_t drow = m;
            if (EPI == 1) {
                int w  = m / Nn;
                int n  = m - w * Nn;
                int b  = w >> 6;
                int wi = w & 63;
                int wh = wi >> 3, ww = wi & 7;
                int i = n / WSz, j = n - (n / WSz) * WSz;
                int hs = wh * WSz + i, ws = ww * WSz + j;
                int h = hs + SSz; if (h >= Hh) h -= Hh;
                int wc = ws + SSz; if (wc >= Ww) wc -= Ww;
                drow = (size_t)(b * (Hh * Ww) + h * Ww + wc);
            }
            #pragma unroll
            for (int nf = 0; nf < 4; nf++) {
                int col = n0 + nbase + nf * 8 + 2 * lcol;
                float2 val;
                val.x = acc[mf][nf][2 * half + 0] + bias[col];
                val.y = acc[mf][nf][2 * half + 1] + bias[col + 1];
                if (EPI == 2) {
                    const float r = 0.70710678118654752f;
                    val.x = 0.5f * val.x * (1.0f + erff(val.x * r));
                    val.y = 0.5f * val.y * (1.0f + erff(val.y * r));
                }
                if (EPI == 1 || EPI == 3) {
                    float2 rv = *reinterpret_cast<const float2*>(&resid[drow * N + col]);
                    val.x += rv.x; val.y += rv.y;
                }
                *reinterpret_cast<float2*>(&C[drow * N + col]) = val;
            }
        }
    }
}

// ---------------------------------------------------------------------------
// Windowed attention (unchanged, fp32)
// ---------------------------------------------------------------------------
__global__ __launch_bounds__(128)
void attn_kernel(const float* __restrict__ qkv,
                 const float* __restrict__ rel_bias,
                 float* __restrict__ out) {
    __shared__ float qs[Nn * HD], ks[Nn * HD], vs[Nn * HD], sc[Nn * Nn];
    int w = blockIdx.x / NHh;
    int h = blockIdx.x - w * NHh;
    int tid = threadIdx.x;
    const float scale = 0.17677669529663687f;
    const float* base = qkv + (size_t)w * Nn * (3 * Cc) + h * HD;

    for (int i = tid; i < Nn * HD / 4; i += 128) {
        int n = i >> 3, d4 = (i & 7) << 2;
        const float* row = base + (size_t)n * (3 * Cc) + d4;
        float4 q4 = *reinterpret_cast<const float4*>(row);
        float4 k4 = *reinterpret_cast<const float4*>(row + Cc);
        float4 v4 = *reinterpret_cast<const float4*>(row + 2 * Cc);
        q4.x *= scale; q4.y *= scale; q4.z *= scale; q4.w *= scale;
        *reinterpret_cast<float4*>(&qs[n * HD + d4]) = q4;
        *reinterpret_cast<float4*>(&ks[n * HD + d4]) = k4;
        *reinterpret_cast<float4*>(&vs[n * HD + d4]) = v4;
    }
    int wi = w & 63;
    int wh = wi >> 3, ww = wi & 7;
    __syncthreads();

    for (int idx = tid; idx < Nn * Nn; idx += 128) {
        int n = idx / Nn, m = idx - (idx / Nn) * Nn;
        float s = 0.f;
        #pragma unroll
        for (int d = 0; d < HD; d += 4) {
            float4 q4 = *reinterpret_cast<const float4*>(&qs[n * HD + d]);
            float4 k4 = *reinterpret_cast<const float4*>(&ks[m * HD + d]);
            s = fmaf(q4.x, k4.x, s); s = fmaf(q4.y, k4.y, s);
            s = fmaf(q4.z, k4.z, s); s = fmaf(q4.w, k4.w, s);
        }
        int ni = n / WSz, nj = n - ni * WSz;
        int mi = m / WSz, mj = m - mi * WSz;
        s += rel_bias[((ni - mi + WSz - 1) * (2 * WSz - 1) + (nj - mj + WSz - 1)) * NHh + h];
        int hn = wh * WSz + ni, hm = wh * WSz + mi;
        int wn = ww * WSz + nj, wm = ww * WSz + mj;
        int rn = (hn < Hh - WSz) ? 0 : ((hn < Hh - SSz) ? 1 : 2);
        int rm = (hm < Hh - WSz) ? 0 : ((hm < Hh - SSz) ? 1 : 2);
        int cn = (wn < Ww - WSz) ? 0 : ((wn < Ww - SSz) ? 1 : 2);
        int cm = (wm < Ww - WSz) ? 0 : ((wm < Ww - SSz) ? 1 : 2);
        if (rn != rm || cn != cm) s -= 100.0f;
        sc[idx] = s;
    }
    __syncthreads();

    int warp = tid >> 5, lane = tid & 31;
    for (int r = warp; r < Nn; r += 4) {
        float v1 = sc[r * Nn + lane];
        float v2 = (lane + 32 < Nn) ? sc[r * Nn + lane + 32] : -1e30f;
        float mx = fmaxf(v1, v2);
        #pragma unroll
        for (int off = 16; off; off >>= 1)
            mx = fmaxf(mx, __shfl_xor_sync(0xffffffffu, mx, off));
        float e1 = expf(v1 - mx);
        float e2 = (lane + 32 < Nn) ? expf(v2 - mx) : 0.f;
        float s = e1 + e2;
        #pragma unroll
        for (int off = 16; off; off >>= 1)
            s += __shfl_xor_sync(0xffffffffu, s, off);
        float inv = 1.0f / s;
        sc[r * Nn + lane] = e1 * inv;
        if (lane + 32 < Nn) sc[r * Nn + lane + 32] = e2 * inv;
    }
    __syncthreads();

    for (int i = tid; i < Nn * HD; i += 128) {
        int n = i >> 5, d = i & 31;
        float s = 0.f;
        #pragma unroll
        for (int m = 0; m < Nn; m++) s = fmaf(sc[n * Nn + m], vs[m * HD + d], s);
        out[((size_t)w * Nn + n) * Cc + h * HD + d] = s;
    }
}

// ---------------------------------------------------------------------------
extern "C" void kernel_launch(void* const* d_in, const int* in_sizes, int n_in,
                              void* d_out, int out_size) {
    const float* x       = (const float*)d_in[0];
    const float* n1g     = (const float*)d_in[1];
    const float* n1b     = (const float*)d_in[2];
    const float* qkv_w   = (const float*)d_in[3];
    const float* qkv_b   = (const float*)d_in[4];
    const float* relb    = (const float*)d_in[5];
    const float* proj_w  = (const float*)d_in[6];
    const float* proj_b  = (const float*)d_in[7];
    const float* n2g     = (const float*)d_in[8];
    const float* n2b     = (const float*)d_in[9];
    const float* fc1_w   = (const float*)d_in[10];
    const float* fc1_b   = (const float*)d_in[11];
    const float* fc2_w   = (const float*)d_in[12];
    const float* fc2_b   = (const float*)d_in[13];
    float* out = (float*)d_out;

    float *xw, *qkv, *ao, *x2, *hid;
    cudaGetSymbolAddress((void**)&xw,  g_xw);
    cudaGetSymbolAddress((void**)&qkv, g_qkv);
    cudaGetSymbolAddress((void**)&ao,  g_ao);
    cudaGetSymbolAddress((void**)&x2,  g_x2);
    cudaGetSymbolAddress((void**)&hid, g_hid);

    const int M = TOK;  // 100352 = 392 * 256

    ln_kernel<true><<<M, Cc>>>(x, n1g, n1b, xw);

    tgemm_kernel<0><<<dim3(3 * Cc / 64, M / 256), 256>>>(
        xw, qkv_w, qkv_b, nullptr, qkv, M, 3 * Cc, Cc);

    attn_kernel<<<2048 * NHh, 128>>>(qkv, relb, ao);

    tgemm_kernel<1><<<dim3(Cc / 64, M / 256), 256>>>(
        ao, proj_w, proj_b, x, x2, M, Cc, Cc);

    ln_kernel<false><<<M, Cc>>>(x2, n2g, n2b, xw);

    tgemm_kernel<2><<<dim3(HID / 64, M / 256), 256>>>(
        xw, fc1_w, fc1_b, nullptr, hid, M, HID, Cc);

    tgemm_kernel<3><<<dim3(Cc / 64, M / 256), 256>>>(
        hid, fc2_w, fc2_b, x2, out, M, Cc, HID);
}